// round 11
// baseline (speedup 1.0000x reference)
#include <cuda_runtime.h>

#define N_NODES 100000
#define N_EDGES 1600000
#define F_IN 128
#define HID 64
#define C_OUT 16

#define H4 (HID / 4)      // 16 float4 per node (layer 1)
#define C4 (C_OUT / 4)    // 4  float4 per node (layer 2)

#define SCAN_B 1024
#define NB_SCAN ((N_NODES + SCAN_B - 1) / SCAN_B)   // 98

#define G1_ROWS 128       // rows per gemm1 block
#define G1_KC 32          // k-chunk
#define XS_STRIDE 36      // padded floats per row in x smem tile
#define WT_STRIDE 33      // padded floats per col in transposed W smem

// ---- static device scratch; float4-typed => guaranteed 16B alignment ----
__device__ float4 g_h1[(size_t)N_NODES * H4];    // x @ W1
__device__ float4 g_rel[(size_t)N_NODES * H4];   // relu(layer-1 output)
__device__ float4 g_h2[(size_t)N_NODES * C4];    // relu_h @ W2
__device__ float g_deg[N_NODES];
__device__ float g_dinv1[N_NODES];
__device__ float g_dinv2[N_NODES];
__device__ int   g_cnt[N_NODES];
__device__ int   g_base[N_NODES + 1];
__device__ int   g_cur[N_NODES];
__device__ int   g_bsum[NB_SCAN];
__device__ int2  g_sre[N_EDGES];     // sorted (row, weight-bits) per edge
__device__ unsigned g_minbits;   // min float bit-pattern among row==0 edges
__device__ int   g_minidx;       // min edge index among bit-exact matches
__device__ float g_wmin;
__device__ int   g_target;       // col[deleted edge]
__device__ int   g_zrow;         // row[deleted edge]
__device__ int   g_is64;         // edge_index stored as int64?

// ---- dtype-robust edge_index accessors ----
__device__ __forceinline__ int load_row(const void* ei, int e) {
    if (g_is64) return (int)((const long long*)ei)[e];
    return ((const int*)ei)[e];
}
__device__ __forceinline__ int load_col(const void* ei, int e) {
    if (g_is64) return (int)((const long long*)ei)[(size_t)N_EDGES + e];
    return ((const int*)ei)[(size_t)N_EDGES + e];
}

// ---- detect edge_index dtype: int64 layout has all-zero odd 32-bit words ----
__global__ void k_detect(const int* __restrict__ ei32) {
    int allzero = 1;
    for (int i = 0; i < 64; i++)
        if (ei32[2 * i + 1] != 0) { allzero = 0; break; }
    g_is64 = allzero;
}

// ---- init: zero counters/degrees, init argmin state ----
__global__ void __launch_bounds__(256) k_init() {
    int i = blockIdx.x * 256 + threadIdx.x;
    if (i == 0) { g_minbits = 0xFFFFFFFFu; g_minidx = 0x7FFFFFFF; }
    if (i < N_NODES) { g_deg[i] = 0.f; g_cnt[i] = 0; }
}

// ---- degrees + per-col edge count + min-weight bits among row==0 edges ----
__global__ void __launch_bounds__(256) k_deg(const void* __restrict__ ei,
                                             const float* __restrict__ ew) {
    int e = blockIdx.x * 256 + threadIdx.x;
    if (e >= N_EDGES) return;
    float w = ew[e];
    int c = load_col(ei, e);
    atomicAdd(&g_deg[c], w);
    atomicAdd(&g_cnt[c], 1);
    int r = load_row(ei, e);
    if (r == 0) {
        // weights are non-negative: IEEE bit pattern is order-preserving.
        atomicMin(&g_minbits, __float_as_uint(w));
    }
}

// ==== GEMM1 v3: register-tiled, f32x2 packed along K (zero dup-movs) ====
// Block: 128 rows x 64 cols, 256 threads. Thread (tr=tid>>4, tc=tid&15) owns
// rows {i*16+tr} x cols {tc*4..tc*4+3}. Each acc is f32x2: lo=even-k, hi=odd-k.
union F4U2 { float4 f4; unsigned long long u2[2]; };

__device__ __forceinline__ void fma2(unsigned long long& acc,
                                     unsigned long long a,
                                     unsigned long long b) {
    asm("fma.rn.f32x2 %0, %1, %2, %0;" : "+l"(acc) : "l"(a), "l"(b));
}
__device__ __forceinline__ float sum2(unsigned long long v) {
    float lo, hi;
    asm("mov.b64 {%0, %1}, %2;" : "=f"(lo), "=f"(hi) : "l"(v));
    return lo + hi;
}

__global__ void __launch_bounds__(256) k_gemm1(const float* __restrict__ x,
                                               const float* __restrict__ W1) {
    __shared__ float Xs[G1_ROWS * XS_STRIDE];   // 18432 B
    __shared__ float Wt[HID * WT_STRIDE];       // 8448 B (transposed chunk)

    const int tid = threadIdx.x;
    const int tc = tid & 15;
    const int tr = tid >> 4;
    const int rb = blockIdx.x * G1_ROWS;

    unsigned long long acc[8][4];
#pragma unroll
    for (int i = 0; i < 8; i++)
#pragma unroll
        for (int c = 0; c < 4; c++) acc[i][c] = 0ULL;

    for (int kc = 0; kc < F_IN / G1_KC; kc++) {
        const int k0 = kc * G1_KC;
        // W chunk, transposed: Wt[col][kloc] = W1[k0+kloc][col]
#pragma unroll
        for (int i = tid; i < (G1_KC * HID) / 4; i += 256) {
            int kloc = i >> 4, cg = i & 15;
            float4 w = *(const float4*)&W1[(size_t)(k0 + kloc) * HID + cg * 4];
            Wt[(cg * 4 + 0) * WT_STRIDE + kloc] = w.x;
            Wt[(cg * 4 + 1) * WT_STRIDE + kloc] = w.y;
            Wt[(cg * 4 + 2) * WT_STRIDE + kloc] = w.z;
            Wt[(cg * 4 + 3) * WT_STRIDE + kloc] = w.w;
        }
        // X chunk: 128 rows x 32 k
#pragma unroll
        for (int i = tid; i < G1_ROWS * (G1_KC / 4); i += 256) {
            int r = i >> 3, seg = i & 7;
            float4 v = make_float4(0.f, 0.f, 0.f, 0.f);
            if (rb + r < N_NODES)
                v = *(const float4*)&x[(size_t)(rb + r) * F_IN + k0 + seg * 4];
            *(float4*)&Xs[r * XS_STRIDE + seg * 4] = v;
        }
        __syncthreads();

#pragma unroll
        for (int k2 = 0; k2 < G1_KC / 4; k2++) {
            F4U2 xv[8], wv[4];
#pragma unroll
            for (int i = 0; i < 8; i++)
                xv[i].f4 = *(const float4*)&Xs[(i * 16 + tr) * XS_STRIDE + k2 * 4];
#pragma unroll
            for (int c = 0; c < 4; c++)
                wv[c].f4 = *(const float4*)&Wt[(tc * 4 + c) * WT_STRIDE + k2 * 4];
#pragma unroll
            for (int i = 0; i < 8; i++)
#pragma unroll
                for (int c = 0; c < 4; c++) {
                    fma2(acc[i][c], xv[i].u2[0], wv[c].u2[0]);
                    fma2(acc[i][c], xv[i].u2[1], wv[c].u2[1]);
                }
        }
        __syncthreads();
    }

#pragma unroll
    for (int i = 0; i < 8; i++) {
        int row = rb + i * 16 + tr;
        if (row < N_NODES) {
            float4 o;
            o.x = sum2(acc[i][0]);
            o.y = sum2(acc[i][1]);
            o.z = sum2(acc[i][2]);
            o.w = sum2(acc[i][3]);
            g_h1[(size_t)row * H4 + tc] = o;
        }
    }
}

// ---- exclusive scan of g_cnt -> g_base ----
__global__ void __launch_bounds__(SCAN_B) k_scan1() {
    __shared__ int s[SCAN_B];
    int i = blockIdx.x * SCAN_B + threadIdx.x;
    int v = (i < N_NODES) ? g_cnt[i] : 0;
    s[threadIdx.x] = v;
    __syncthreads();
    for (int off = 1; off < SCAN_B; off <<= 1) {   // Hillis-Steele inclusive
        int t = (threadIdx.x >= off) ? s[threadIdx.x - off] : 0;
        __syncthreads();
        s[threadIdx.x] += t;
        __syncthreads();
    }
    if (i < N_NODES) g_base[i] = s[threadIdx.x] - v;   // local exclusive
    if (threadIdx.x == SCAN_B - 1) g_bsum[blockIdx.x] = s[SCAN_B - 1];
}

__global__ void k_scan2() {  // single thread: 98 adds
    int run = 0;
    for (int b = 0; b < NB_SCAN; b++) {
        int v = g_bsum[b];
        g_bsum[b] = run;
        run += v;
    }
}

// ---- finalize scan + dinv1 (fused per-node pass) ----
__global__ void __launch_bounds__(256) k_scan3() {
    int i = blockIdx.x * 256 + threadIdx.x;
    if (i >= N_NODES) return;
    int b = g_base[i] + g_bsum[i / SCAN_B];
    g_base[i] = b;
    g_cur[i] = b;
    g_dinv1[i] = rsqrtf(g_deg[i] + 1.0f);
    if (i == 0) g_base[N_NODES] = N_EDGES;
}

// ---- bucket edges by destination column; also resolve argmin index ----
__global__ void __launch_bounds__(256) k_place(const void* __restrict__ ei,
                                               const float* __restrict__ ew) {
    int e = blockIdx.x * 256 + threadIdx.x;
    if (e >= N_EDGES) return;
    int r = load_row(ei, e);
    int c = load_col(ei, e);
    float w = ew[e];
    int pos = atomicAdd(&g_cur[c], 1);
    g_sre[pos] = make_int2(r, __float_as_int(w));
    if (r == 0 && __float_as_uint(w) == g_minbits)
        atomicMin(&g_minidx, e);   // first occurrence of the min (jnp.argmin)
}

// ---- extract deleted-edge info (single thread) ----
__global__ void k_extract(const void* __restrict__ ei,
                          const float* __restrict__ ew) {
    int idx = (g_minidx == 0x7FFFFFFF) ? 0 : g_minidx; // all-inf mask -> argmin 0
    g_wmin = ew[idx];
    g_target = load_col(ei, idx);
    g_zrow = load_row(ei, idx);
}

__global__ void __launch_bounds__(256) k_dinv2() {
    int i = blockIdx.x * 256 + threadIdx.x;
    if (i >= N_NODES) return;
    float sub = (i == g_target) ? g_wmin : 0.f;
    g_dinv2[i] = rsqrtf(g_deg[i] + 1.0f - sub);
}

// ---- zero the deleted edge's record inside its destination bucket.
// Any record in this bucket with matching (row, weight-bits) is mathematically
// interchangeable with the argmin edge, so zeroing the first match is exact.
// MUST run after k_gather1 (layer 1 uses original weights). ----
__global__ void k_zap() {
    int s = g_base[g_target], e_end = g_base[g_target + 1];
    int wb = __float_as_int(g_wmin);
    int zr = g_zrow;
    for (int i = s; i < e_end; i++) {
        int2 md = g_sre[i];
        if (md.x == zr && md.y == wb) { g_sre[i].y = 0; break; } // 0 bits == 0.0f
    }
}

// ---- layer-1 gather + epilogue: 16 lanes per node, shfl-staged metadata ----
// out = relu( dinv1[c] * sum_e dinv1[row]*w*h1[row]  +  dinv1[c]^2*h1[c] + b1 )
__global__ void __launch_bounds__(256) k_gather1(const float* __restrict__ b1) {
    int t = blockIdx.x * 256 + threadIdx.x;
    int node = t >> 4;
    int lane = t & 15;
    if (node >= N_NODES) return;   // never taken (1.6M threads exactly)
    unsigned hm = (threadIdx.x & 16) ? 0xffff0000u : 0x0000ffffu;
    int s = g_base[node], e_end = g_base[node + 1];

    float4 acc = make_float4(0.f, 0.f, 0.f, 0.f);
    for (int base = s; base < e_end; base += 16) {
        int n = min(16, e_end - base);
        int r0 = 0; float cf = 0.f;
        if (base + lane < e_end) {
            int2 md = g_sre[base + lane];          // coalesced 16x8B
            r0 = md.x;
            cf = g_dinv1[r0] * __int_as_float(md.y);
        }
        for (int j = 0; j < n; j++) {
            float coef = __shfl_sync(hm, cf, j, 16);
            int r = __shfl_sync(hm, r0, j, 16);
            float4 hv = g_h1[(size_t)r * H4 + lane];
            acc.x += coef * hv.x; acc.y += coef * hv.y;
            acc.z += coef * hv.z; acc.w += coef * hv.w;
        }
    }
    float dc = g_dinv1[node];
    float dc2 = dc * dc;
    float4 hme = g_h1[(size_t)node * H4 + lane];
    float4 bb = *(const float4*)&b1[lane * 4];
    float4 o;
    o.x = fmaxf(dc * acc.x + dc2 * hme.x + bb.x, 0.f);
    o.y = fmaxf(dc * acc.y + dc2 * hme.y + bb.y, 0.f);
    o.z = fmaxf(dc * acc.z + dc2 * hme.z + bb.z, 0.f);
    o.w = fmaxf(dc * acc.w + dc2 * hme.w + bb.w, 0.f);
    g_rel[(size_t)node * H4 + lane] = o;
}

// ---- GEMM2: g_h2 = g_rel @ W2 ----
__global__ void __launch_bounds__(256) k_gemm2(const float* __restrict__ W2) {
    __shared__ float4 Ws4[(HID * C_OUT) / 4]; // 256 float4
    if (threadIdx.x < (HID * C_OUT) / 4)
        Ws4[threadIdx.x] = ((const float4*)W2)[threadIdx.x];
    __syncthreads();
    const float* Ws = (const float*)Ws4;

    int row = blockIdx.x * 256 + threadIdx.x;
    if (row >= N_NODES) return;

    float acc[C_OUT];
#pragma unroll
    for (int j = 0; j < C_OUT; j++) acc[j] = 0.f;

    const float4* xr = &g_rel[(size_t)row * H4];
#pragma unroll
    for (int k4 = 0; k4 < HID / 4; k4++) {
        float4 xv = xr[k4];
        const float* wk = Ws + k4 * 4 * C_OUT;
#pragma unroll
        for (int j = 0; j < C_OUT; j += 4) {
            float4 w0 = *(const float4*)(wk + j);
            float4 w1 = *(const float4*)(wk + C_OUT + j);
            float4 w2 = *(const float4*)(wk + 2 * C_OUT + j);
            float4 w3 = *(const float4*)(wk + 3 * C_OUT + j);
            acc[j + 0] += xv.x * w0.x + xv.y * w1.x + xv.z * w2.x + xv.w * w3.x;
            acc[j + 1] += xv.x * w0.y + xv.y * w1.y + xv.z * w2.y + xv.w * w3.y;
            acc[j + 2] += xv.x * w0.z + xv.y * w1.z + xv.z * w2.z + xv.w * w3.z;
            acc[j + 3] += xv.x * w0.w + xv.y * w1.w + xv.z * w2.w + xv.w * w3.w;
        }
    }
    float4* outr = &g_h2[(size_t)row * C4];
#pragma unroll
    for (int j = 0; j < C_OUT; j += 4)
        outr[j / 4] = make_float4(acc[j], acc[j + 1], acc[j + 2], acc[j + 3]);
}

// ---- layer-2 gather + epilogue: 4 lanes per node (deleted edge pre-zeroed) ----
__global__ void __launch_bounds__(256) k_gather2(const float* __restrict__ b2,
                                                 float* __restrict__ out) {
    int t = blockIdx.x * 256 + threadIdx.x;
    int node = t >> 2;
    int lane = t & 3;
    if (node >= N_NODES) return;
    int s = g_base[node], e_end = g_base[node + 1];

    float4 acc = make_float4(0.f, 0.f, 0.f, 0.f);
    for (int e = s; e < e_end; e++) {
        int2 md = g_sre[e];
        float coef = g_dinv2[md.x] * __int_as_float(md.y);
        float4 hv = g_h2[(size_t)md.x * C4 + lane];
        acc.x += coef * hv.x; acc.y += coef * hv.y;
        acc.z += coef * hv.z; acc.w += coef * hv.w;
    }
    float dc = g_dinv2[node];
    float dc2 = dc * dc;
    float4 hme = g_h2[(size_t)node * C4 + lane];
    float4 bb = *(const float4*)&b2[lane * 4];
    float4 o;
    o.x = dc * acc.x + dc2 * hme.x + bb.x;
    o.y = dc * acc.y + dc2 * hme.y + bb.y;
    o.z = dc * acc.z + dc2 * hme.z + bb.z;
    o.w = dc * acc.w + dc2 * hme.w + bb.w;
    ((float4*)out)[(size_t)node * C4 + lane] = o;
}

extern "C" void kernel_launch(void* const* d_in, const int* in_sizes, int n_in,
                              void* d_out, int out_size) {
    const float* x  = (const float*)d_in[0];
    const void*  ei = d_in[1];
    const float* ew = (const float*)d_in[2];
    const float* W1 = (const float*)d_in[3];
    const float* b1 = (const float*)d_in[4];
    const float* W2 = (const float*)d_in[5];
    const float* b2 = (const float*)d_in[6];
    float* out = (float*)d_out;

    (void)in_sizes; (void)n_in; (void)out_size;

    int nb_nodes = (N_NODES + 255) / 256;
    int nb_edges = (N_EDGES + 255) / 256;
    int nb_g1 = (N_NODES + G1_ROWS - 1) / G1_ROWS;

    k_detect<<<1, 1>>>((const int*)ei);
    k_init<<<nb_nodes, 256>>>();
    k_deg<<<nb_edges, 256>>>(ei, ew);
    k_gemm1<<<nb_g1, 256>>>(x, W1);
    k_scan1<<<NB_SCAN, SCAN_B>>>();
    k_scan2<<<1, 1>>>();
    k_scan3<<<nb_nodes, 256>>>();
    k_place<<<nb_edges, 256>>>(ei, ew);
    k_extract<<<1, 1>>>(ei, ew);
    k_dinv2<<<nb_nodes, 256>>>();
    k_gather1<<<(int)(((long)N_NODES * 16 + 255) / 256), 256>>>(b1);
    k_zap<<<1, 1>>>();   // after gather1 (layer 1 uses original weights)
    k_gemm2<<<nb_nodes, 256>>>(W2);
    k_gather2<<<(int)(((long)N_NODES * 4 + 255) / 256), 256>>>(b2, out);
}

// round 12
// speedup vs baseline: 1.1310x; 1.1310x over previous
#include <cuda_runtime.h>

#define N_NODES 100000
#define N_EDGES 1600000
#define F_IN 128
#define HID 64
#define C_OUT 16

#define H4 (HID / 4)      // 16 float4 per node (layer 1)
#define C4 (C_OUT / 4)    // 4  float4 per node (layer 2)

#define SCAN_B 1024
#define NB_SCAN ((N_NODES + SCAN_B - 1) / SCAN_B)   // 98

#define G1_ROWS 128       // rows per gemm1 block
#define G1_KC 32          // k-chunk
#define XS_STRIDE 36      // padded floats per row in x smem tile

// ---- static device scratch; float4-typed => guaranteed 16B alignment ----
__device__ float4 g_h1[(size_t)N_NODES * H4];    // x @ W1
__device__ float4 g_rel[(size_t)N_NODES * H4];   // relu(layer-1 output)
__device__ float4 g_h2[(size_t)N_NODES * C4];    // relu_h @ W2
__device__ float g_deg[N_NODES];
__device__ float g_dinv1[N_NODES];
__device__ float g_dinv2[N_NODES];
__device__ int   g_cnt[N_NODES];
__device__ int   g_base[N_NODES + 1];
__device__ int   g_cur[N_NODES];
__device__ int   g_bsum[NB_SCAN];
__device__ int2  g_sre[N_EDGES];     // sorted (row, weight-bits) per edge
__device__ unsigned g_minbits;   // min float bit-pattern among row==0 edges
__device__ int   g_minidx;       // min edge index among bit-exact matches
__device__ float g_wmin;
__device__ int   g_target;       // col[deleted edge]
__device__ int   g_zrow;         // row[deleted edge]
__device__ int   g_is64;         // edge_index stored as int64?

// ---- dtype-robust edge_index accessors ----
__device__ __forceinline__ int load_row(const void* ei, int e) {
    if (g_is64) return (int)((const long long*)ei)[e];
    return ((const int*)ei)[e];
}
__device__ __forceinline__ int load_col(const void* ei, int e) {
    if (g_is64) return (int)((const long long*)ei)[(size_t)N_EDGES + e];
    return ((const int*)ei)[(size_t)N_EDGES + e];
}

// ---- init: zero counters/degrees, init argmin state, detect ei dtype ----
__global__ void __launch_bounds__(256) k_init(const int* __restrict__ ei32) {
    int i = blockIdx.x * 256 + threadIdx.x;
    if (i == 0) {
        g_minbits = 0xFFFFFFFFu;
        g_minidx = 0x7FFFFFFF;
        // int64 layout has all-zero odd 32-bit words (indices < 2^31)
        int allzero = 1;
        for (int j = 0; j < 64; j++)
            if (ei32[2 * j + 1] != 0) { allzero = 0; break; }
        g_is64 = allzero;
    }
    if (i < N_NODES) { g_deg[i] = 0.f; g_cnt[i] = 0; }
}

// ---- degrees + per-col edge count + min-weight bits among row==0 edges ----
__global__ void __launch_bounds__(256) k_deg(const void* __restrict__ ei,
                                             const float* __restrict__ ew) {
    int e = blockIdx.x * 256 + threadIdx.x;
    if (e >= N_EDGES) return;
    float w = ew[e];
    int c = load_col(ei, e);
    atomicAdd(&g_deg[c], w);
    atomicAdd(&g_cnt[c], 1);
    int r = load_row(ei, e);
    if (r == 0) {
        // weights are non-negative: IEEE bit pattern is order-preserving.
        atomicMin(&g_minbits, __float_as_uint(w));
    }
}

// ==== GEMM1 (R7-proven): register-tiled, f32x2 packed along N ====
// Block: 128 rows x 64 cols. Thread (tr = tid>>4, tc = tid&15) computes
// rows {i*16 + tr, i=0..7} x cols {tc*4 .. tc*4+3}. Accumulators are 16 f32x2.
union F4U2 { float4 f4; unsigned long long u2[2]; };

__device__ __forceinline__ void fma2(unsigned long long& acc,
                                     unsigned long long a,
                                     unsigned long long b) {
    asm("fma.rn.f32x2 %0, %1, %2, %0;" : "+l"(acc) : "l"(a), "l"(b));
}
__device__ __forceinline__ unsigned long long dup2(float v) {
    unsigned long long d;
    asm("mov.b64 %0, {%1, %1};" : "=l"(d) : "f"(v));
    return d;
}

__global__ void __launch_bounds__(256) k_gemm1(const float* __restrict__ x,
                                               const float* __restrict__ W1) {
    __shared__ float Xs[G1_ROWS * XS_STRIDE];   // 18432 B
    __shared__ float Wcs[G1_KC * HID];          // 8192 B

    const int tid = threadIdx.x;
    const int tc = tid & 15;
    const int tr = tid >> 4;
    const int rb = blockIdx.x * G1_ROWS;

    unsigned long long acc[8][2];
#pragma unroll
    for (int i = 0; i < 8; i++) { acc[i][0] = 0ULL; acc[i][1] = 0ULL; }

    for (int kc = 0; kc < F_IN / G1_KC; kc++) {
        const int k0 = kc * G1_KC;
        // fill W chunk: rows k0..k0+31 of W1 are contiguous (row-major [128][64])
#pragma unroll
        for (int i = tid; i < (G1_KC * HID) / 4; i += 256)
            *(float4*)&Wcs[i * 4] = ((const float4*)(W1 + k0 * HID))[i];
        // fill X chunk: 128 rows x 32 k
#pragma unroll
        for (int i = tid; i < G1_ROWS * (G1_KC / 4); i += 256) {
            int r = i >> 3, seg = i & 7;
            float4 v = make_float4(0.f, 0.f, 0.f, 0.f);
            if (rb + r < N_NODES)
                v = *(const float4*)&x[(size_t)(rb + r) * F_IN + k0 + seg * 4];
            *(float4*)&Xs[r * XS_STRIDE + seg * 4] = v;
        }
        __syncthreads();

#pragma unroll
        for (int k4 = 0; k4 < G1_KC / 4; k4++) {
            float4 xv[8];
#pragma unroll
            for (int i = 0; i < 8; i++)
                xv[i] = *(const float4*)&Xs[(i * 16 + tr) * XS_STRIDE + k4 * 4];
            F4U2 wv[4];
#pragma unroll
            for (int kk = 0; kk < 4; kk++)
                wv[kk].f4 = *(const float4*)&Wcs[(k4 * 4 + kk) * HID + tc * 4];
#pragma unroll
            for (int i = 0; i < 8; i++) {
                float xs0 = xv[i].x, xs1 = xv[i].y, xs2 = xv[i].z, xs3 = xv[i].w;
                unsigned long long a;
                a = dup2(xs0); fma2(acc[i][0], a, wv[0].u2[0]); fma2(acc[i][1], a, wv[0].u2[1]);
                a = dup2(xs1); fma2(acc[i][0], a, wv[1].u2[0]); fma2(acc[i][1], a, wv[1].u2[1]);
                a = dup2(xs2); fma2(acc[i][0], a, wv[2].u2[0]); fma2(acc[i][1], a, wv[2].u2[1]);
                a = dup2(xs3); fma2(acc[i][0], a, wv[3].u2[0]); fma2(acc[i][1], a, wv[3].u2[1]);
            }
        }
        __syncthreads();
    }

    // epilogue: unpack and store float4 per (row, col-group)
#pragma unroll
    for (int i = 0; i < 8; i++) {
        int row = rb + i * 16 + tr;
        if (row < N_NODES) {
            F4U2 o;
            o.u2[0] = acc[i][0];
            o.u2[1] = acc[i][1];
            g_h1[(size_t)row * H4 + tc] = o.f4;
        }
    }
}

// ---- exclusive scan of g_cnt -> g_base ----
__global__ void __launch_bounds__(SCAN_B) k_scan1() {
    __shared__ int s[SCAN_B];
    int i = blockIdx.x * SCAN_B + threadIdx.x;
    int v = (i < N_NODES) ? g_cnt[i] : 0;
    s[threadIdx.x] = v;
    __syncthreads();
    for (int off = 1; off < SCAN_B; off <<= 1) {   // Hillis-Steele inclusive
        int t = (threadIdx.x >= off) ? s[threadIdx.x - off] : 0;
        __syncthreads();
        s[threadIdx.x] += t;
        __syncthreads();
    }
    if (i < N_NODES) g_base[i] = s[threadIdx.x] - v;   // local exclusive
    if (threadIdx.x == SCAN_B - 1) g_bsum[blockIdx.x] = s[SCAN_B - 1];
}

__global__ void k_scan2() {  // single thread: 98 adds
    int run = 0;
    for (int b = 0; b < NB_SCAN; b++) {
        int v = g_bsum[b];
        g_bsum[b] = run;
        run += v;
    }
}

// ---- finalize scan + dinv1 (fused per-node pass) ----
__global__ void __launch_bounds__(256) k_scan3() {
    int i = blockIdx.x * 256 + threadIdx.x;
    if (i >= N_NODES) return;
    int b = g_base[i] + g_bsum[i / SCAN_B];
    g_base[i] = b;
    g_cur[i] = b;
    g_dinv1[i] = rsqrtf(g_deg[i] + 1.0f);
    if (i == 0) g_base[N_NODES] = N_EDGES;
}

// ---- bucket edges by destination column; also resolve argmin index ----
__global__ void __launch_bounds__(256) k_place(const void* __restrict__ ei,
                                               const float* __restrict__ ew) {
    int e = blockIdx.x * 256 + threadIdx.x;
    if (e >= N_EDGES) return;
    int r = load_row(ei, e);
    int c = load_col(ei, e);
    float w = ew[e];
    int pos = atomicAdd(&g_cur[c], 1);
    g_sre[pos] = make_int2(r, __float_as_int(w));
    if (r == 0 && __float_as_uint(w) == g_minbits)
        atomicMin(&g_minidx, e);   // first occurrence of the min (jnp.argmin)
}

// ---- extract deleted-edge info (single thread) ----
__global__ void k_extract(const void* __restrict__ ei,
                          const float* __restrict__ ew) {
    int idx = (g_minidx == 0x7FFFFFFF) ? 0 : g_minidx; // all-inf mask -> argmin 0
    g_wmin = ew[idx];
    g_target = load_col(ei, idx);
    g_zrow = load_row(ei, idx);
}

__global__ void __launch_bounds__(256) k_dinv2() {
    int i = blockIdx.x * 256 + threadIdx.x;
    if (i >= N_NODES) return;
    float sub = (i == g_target) ? g_wmin : 0.f;
    g_dinv2[i] = rsqrtf(g_deg[i] + 1.0f - sub);
}

// ---- layer-1 gather + epilogue: 16 lanes per node, shfl-staged metadata ----
// out = relu( dinv1[c] * sum_e dinv1[row]*w*h1[row]  +  dinv1[c]^2*h1[c] + b1 )
__global__ void __launch_bounds__(256) k_gather1(const float* __restrict__ b1) {
    int t = blockIdx.x * 256 + threadIdx.x;
    int node = t >> 4;
    int lane = t & 15;
    if (node >= N_NODES) return;   // never taken (1.6M threads exactly)
    unsigned hm = (threadIdx.x & 16) ? 0xffff0000u : 0x0000ffffu;
    int s = g_base[node], e_end = g_base[node + 1];

    float4 acc = make_float4(0.f, 0.f, 0.f, 0.f);
    for (int base = s; base < e_end; base += 16) {
        int n = min(16, e_end - base);
        int r0 = 0; float cf = 0.f;
        if (base + lane < e_end) {
            int2 md = g_sre[base + lane];          // coalesced 16x8B
            r0 = md.x;
            cf = g_dinv1[r0] * __int_as_float(md.y);
        }
        for (int j = 0; j < n; j++) {
            float coef = __shfl_sync(hm, cf, j, 16);
            int r = __shfl_sync(hm, r0, j, 16);
            float4 hv = g_h1[(size_t)r * H4 + lane];
            acc.x += coef * hv.x; acc.y += coef * hv.y;
            acc.z += coef * hv.z; acc.w += coef * hv.w;
        }
    }
    float dc = g_dinv1[node];
    float dc2 = dc * dc;
    float4 hme = g_h1[(size_t)node * H4 + lane];
    float4 bb = *(const float4*)&b1[lane * 4];
    float4 o;
    o.x = fmaxf(dc * acc.x + dc2 * hme.x + bb.x, 0.f);
    o.y = fmaxf(dc * acc.y + dc2 * hme.y + bb.y, 0.f);
    o.z = fmaxf(dc * acc.z + dc2 * hme.z + bb.z, 0.f);
    o.w = fmaxf(dc * acc.w + dc2 * hme.w + bb.w, 0.f);
    g_rel[(size_t)node * H4 + lane] = o;
}

// ---- GEMM2: g_h2 = g_rel @ W2 ----
__global__ void __launch_bounds__(256) k_gemm2(const float* __restrict__ W2) {
    __shared__ float4 Ws4[(HID * C_OUT) / 4]; // 256 float4
    if (threadIdx.x < (HID * C_OUT) / 4)
        Ws4[threadIdx.x] = ((const float4*)W2)[threadIdx.x];
    __syncthreads();
    const float* Ws = (const float*)Ws4;

    int row = blockIdx.x * 256 + threadIdx.x;
    if (row >= N_NODES) return;

    float acc[C_OUT];
#pragma unroll
    for (int j = 0; j < C_OUT; j++) acc[j] = 0.f;

    const float4* xr = &g_rel[(size_t)row * H4];
#pragma unroll
    for (int k4 = 0; k4 < HID / 4; k4++) {
        float4 xv = xr[k4];
        const float* wk = Ws + k4 * 4 * C_OUT;
#pragma unroll
        for (int j = 0; j < C_OUT; j += 4) {
            float4 w0 = *(const float4*)(wk + j);
            float4 w1 = *(const float4*)(wk + C_OUT + j);
            float4 w2 = *(const float4*)(wk + 2 * C_OUT + j);
            float4 w3 = *(const float4*)(wk + 3 * C_OUT + j);
            acc[j + 0] += xv.x * w0.x + xv.y * w1.x + xv.z * w2.x + xv.w * w3.x;
            acc[j + 1] += xv.x * w0.y + xv.y * w1.y + xv.z * w2.y + xv.w * w3.y;
            acc[j + 2] += xv.x * w0.z + xv.y * w1.z + xv.z * w2.z + xv.w * w3.z;
            acc[j + 3] += xv.x * w0.w + xv.y * w1.w + xv.z * w2.w + xv.w * w3.w;
        }
    }
    float4* outr = &g_h2[(size_t)row * C4];
#pragma unroll
    for (int j = 0; j < C_OUT; j += 4)
        outr[j / 4] = make_float4(acc[j], acc[j + 1], acc[j + 2], acc[j + 3]);
}

// ---- layer-2 gather + epilogue: 4 lanes per node; inline first-match skip
// of the deleted edge (same semantics as a zap pass: exactly one record with
// matching (row, weight-bits) in the target bucket contributes 0). ----
__global__ void __launch_bounds__(256) k_gather2(const float* __restrict__ b2,
                                                 float* __restrict__ out) {
    int t = blockIdx.x * 256 + threadIdx.x;
    int node = t >> 2;
    int lane = t & 3;
    if (node >= N_NODES) return;
    int s = g_base[node], e_end = g_base[node + 1];

    bool active = (node == g_target);   // this node owns the deleted edge
    int zr = g_zrow;
    int wb = __float_as_int(g_wmin);
    bool skipped = false;

    float4 acc = make_float4(0.f, 0.f, 0.f, 0.f);
    for (int e = s; e < e_end; e++) {
        int2 md = g_sre[e];
        if (active && !skipped && md.x == zr && md.y == wb) {
            skipped = true;            // deterministic: same order in all 4 lanes
            continue;
        }
        float coef = g_dinv2[md.x] * __int_as_float(md.y);
        float4 hv = g_h2[(size_t)md.x * C4 + lane];
        acc.x += coef * hv.x; acc.y += coef * hv.y;
        acc.z += coef * hv.z; acc.w += coef * hv.w;
    }
    float dc = g_dinv2[node];
    float dc2 = dc * dc;
    float4 hme = g_h2[(size_t)node * C4 + lane];
    float4 bb = *(const float4*)&b2[lane * 4];
    float4 o;
    o.x = dc * acc.x + dc2 * hme.x + bb.x;
    o.y = dc * acc.y + dc2 * hme.y + bb.y;
    o.z = dc * acc.z + dc2 * hme.z + bb.z;
    o.w = dc * acc.w + dc2 * hme.w + bb.w;
    ((float4*)out)[(size_t)node * C4 + lane] = o;
}

extern "C" void kernel_launch(void* const* d_in, const int* in_sizes, int n_in,
                              void* d_out, int out_size) {
    const float* x  = (const float*)d_in[0];
    const void*  ei = d_in[1];
    const float* ew = (const float*)d_in[2];
    const float* W1 = (const float*)d_in[3];
    const float* b1 = (const float*)d_in[4];
    const float* W2 = (const float*)d_in[5];
    const float* b2 = (const float*)d_in[6];
    float* out = (float*)d_out;

    (void)in_sizes; (void)n_in; (void)out_size;

    int nb_nodes = (N_NODES + 255) / 256;
    int nb_edges = (N_EDGES + 255) / 256;
    int nb_g1 = (N_NODES + G1_ROWS - 1) / G1_ROWS;

    k_init<<<nb_nodes, 256>>>((const int*)ei);
    k_deg<<<nb_edges, 256>>>(ei, ew);
    k_gemm1<<<nb_g1, 256>>>(x, W1);
    k_scan1<<<NB_SCAN, SCAN_B>>>();
    k_scan2<<<1, 1>>>();
    k_scan3<<<nb_nodes, 256>>>();
    k_place<<<nb_edges, 256>>>(ei, ew);
    k_extract<<<1, 1>>>(ei, ew);
    k_dinv2<<<nb_nodes, 256>>>();
    k_gather1<<<(int)(((long)N_NODES * 16 + 255) / 256), 256>>>(b1);
    k_gemm2<<<nb_nodes, 256>>>(W2);
    k_gather2<<<(int)(((long)N_NODES * 4 + 255) / 256), 256>>>(b2, out);
}

// round 15
// speedup vs baseline: 1.1676x; 1.0323x over previous
#include <cuda_runtime.h>

#define N_NODES 100000
#define N_EDGES 1600000
#define F_IN 128
#define HID 64
#define C_OUT 16

#define H4 (HID / 4)      // 16 float4 per node (layer 1)
#define C4 (C_OUT / 4)    // 4  float4 per node (layer 2)

#define SCAN_B 1024
#define NB_SCAN ((N_NODES + SCAN_B - 1) / SCAN_B)   // 98

#define G1_ROWS 128       // rows per gemm1 block
#define G1_KC 32          // k-chunk
#define XS_STRIDE 36      // padded floats per row in x smem tile

// ---- static device scratch; float4-typed => guaranteed 16B alignment ----
__device__ float4 g_h1[(size_t)N_NODES * H4];    // x @ W1
__device__ float4 g_rel[(size_t)N_NODES * H4];   // relu(layer-1 output)
__device__ float4 g_h2[(size_t)N_NODES * C4];    // relu_h @ W2
__device__ float g_deg[N_NODES];
__device__ float g_dinv1[N_NODES];
__device__ float g_dinv2[N_NODES];
__device__ int   g_cnt[N_NODES];
__device__ int   g_base[N_NODES + 1];
__device__ int   g_cur[N_NODES];
__device__ int   g_bsum[NB_SCAN];
__device__ int2  g_sre[N_EDGES];     // sorted (row, weight-bits) per edge
__device__ unsigned g_minbits;   // min float bit-pattern among row==0 edges
__device__ int   g_minidx;       // min edge index among bit-exact matches
__device__ float g_wmin;
__device__ int   g_target;       // col[deleted edge]
__device__ int   g_zrow;         // row[deleted edge]
__device__ int   g_is64;         // edge_index stored as int64?

// ---- dtype-robust edge_index accessors ----
__device__ __forceinline__ int load_row(const void* ei, int e) {
    if (g_is64) return (int)((const long long*)ei)[e];
    return ((const int*)ei)[e];
}
__device__ __forceinline__ int load_col(const void* ei, int e) {
    if (g_is64) return (int)((const long long*)ei)[(size_t)N_EDGES + e];
    return ((const int*)ei)[(size_t)N_EDGES + e];
}

// ---- init: zero counters/degrees, init argmin state, detect ei dtype ----
__global__ void __launch_bounds__(256) k_init(const int* __restrict__ ei32) {
    int i = blockIdx.x * 256 + threadIdx.x;
    if (i == 0) {
        g_minbits = 0xFFFFFFFFu;
        g_minidx = 0x7FFFFFFF;
        // int64 layout has all-zero odd 32-bit words (indices < 2^31)
        int allzero = 1;
        for (int j = 0; j < 64; j++)
            if (ei32[2 * j + 1] != 0) { allzero = 0; break; }
        g_is64 = allzero;
    }
    if (i < N_NODES) { g_deg[i] = 0.f; g_cnt[i] = 0; }
}

// ---- degrees + per-col edge count + min-weight bits among row==0 edges ----
__global__ void __launch_bounds__(256) k_deg(const void* __restrict__ ei,
                                             const float* __restrict__ ew) {
    int e = blockIdx.x * 256 + threadIdx.x;
    if (e >= N_EDGES) return;
    float w = ew[e];
    int c = load_col(ei, e);
    atomicAdd(&g_deg[c], w);
    atomicAdd(&g_cnt[c], 1);
    int r = load_row(ei, e);
    if (r == 0) {
        // weights are non-negative: IEEE bit pattern is order-preserving.
        atomicMin(&g_minbits, __float_as_uint(w));
    }
}

// ==== GEMM1 (R7-proven): register-tiled, f32x2 packed along N ====
// Block: 128 rows x 64 cols. Thread (tr = tid>>4, tc = tid&15) computes
// rows {i*16 + tr, i=0..7} x cols {tc*4 .. tc*4+3}. Accumulators are 16 f32x2.
union F4U2 { float4 f4; unsigned long long u2[2]; };

__device__ __forceinline__ void fma2(unsigned long long& acc,
                                     unsigned long long a,
                                     unsigned long long b) {
    asm("fma.rn.f32x2 %0, %1, %2, %0;" : "+l"(acc) : "l"(a), "l"(b));
}
__device__ __forceinline__ unsigned long long dup2(float v) {
    unsigned long long d;
    asm("mov.b64 %0, {%1, %1};" : "=l"(d) : "f"(v));
    return d;
}

__global__ void __launch_bounds__(256) k_gemm1(const float* __restrict__ x,
                                               const float* __restrict__ W1) {
    __shared__ float Xs[G1_ROWS * XS_STRIDE];   // 18432 B
    __shared__ float Wcs[G1_KC * HID];          // 8192 B

    const int tid = threadIdx.x;
    const int tc = tid & 15;
    const int tr = tid >> 4;
    const int rb = blockIdx.x * G1_ROWS;

    unsigned long long acc[8][2];
#pragma unroll
    for (int i = 0; i < 8; i++) { acc[i][0] = 0ULL; acc[i][1] = 0ULL; }

    for (int kc = 0; kc < F_IN / G1_KC; kc++) {
        const int k0 = kc * G1_KC;
        // fill W chunk: rows k0..k0+31 of W1 are contiguous (row-major [128][64])
#pragma unroll
        for (int i = tid; i < (G1_KC * HID) / 4; i += 256)
            *(float4*)&Wcs[i * 4] = ((const float4*)(W1 + k0 * HID))[i];
        // fill X chunk: 128 rows x 32 k
#pragma unroll
        for (int i = tid; i < G1_ROWS * (G1_KC / 4); i += 256) {
            int r = i >> 3, seg = i & 7;
            float4 v = make_float4(0.f, 0.f, 0.f, 0.f);
            if (rb + r < N_NODES)
                v = *(const float4*)&x[(size_t)(rb + r) * F_IN + k0 + seg * 4];
            *(float4*)&Xs[r * XS_STRIDE + seg * 4] = v;
        }
        __syncthreads();

#pragma unroll
        for (int k4 = 0; k4 < G1_KC / 4; k4++) {
            float4 xv[8];
#pragma unroll
            for (int i = 0; i < 8; i++)
                xv[i] = *(const float4*)&Xs[(i * 16 + tr) * XS_STRIDE + k4 * 4];
            F4U2 wv[4];
#pragma unroll
            for (int kk = 0; kk < 4; kk++)
                wv[kk].f4 = *(const float4*)&Wcs[(k4 * 4 + kk) * HID + tc * 4];
#pragma unroll
            for (int i = 0; i < 8; i++) {
                float xs0 = xv[i].x, xs1 = xv[i].y, xs2 = xv[i].z, xs3 = xv[i].w;
                unsigned long long a;
                a = dup2(xs0); fma2(acc[i][0], a, wv[0].u2[0]); fma2(acc[i][1], a, wv[0].u2[1]);
                a = dup2(xs1); fma2(acc[i][0], a, wv[1].u2[0]); fma2(acc[i][1], a, wv[1].u2[1]);
                a = dup2(xs2); fma2(acc[i][0], a, wv[2].u2[0]); fma2(acc[i][1], a, wv[2].u2[1]);
                a = dup2(xs3); fma2(acc[i][0], a, wv[3].u2[0]); fma2(acc[i][1], a, wv[3].u2[1]);
            }
        }
        __syncthreads();
    }

    // epilogue: unpack and store float4 per (row, col-group)
#pragma unroll
    for (int i = 0; i < 8; i++) {
        int row = rb + i * 16 + tr;
        if (row < N_NODES) {
            F4U2 o;
            o.u2[0] = acc[i][0];
            o.u2[1] = acc[i][1];
            g_h1[(size_t)row * H4 + tc] = o.f4;
        }
    }
}

// ---- exclusive scan of g_cnt -> g_base ----
__global__ void __launch_bounds__(SCAN_B) k_scan1() {
    __shared__ int s[SCAN_B];
    int i = blockIdx.x * SCAN_B + threadIdx.x;
    int v = (i < N_NODES) ? g_cnt[i] : 0;
    s[threadIdx.x] = v;
    __syncthreads();
    for (int off = 1; off < SCAN_B; off <<= 1) {   // Hillis-Steele inclusive
        int t = (threadIdx.x >= off) ? s[threadIdx.x - off] : 0;
        __syncthreads();
        s[threadIdx.x] += t;
        __syncthreads();
    }
    if (i < N_NODES) g_base[i] = s[threadIdx.x] - v;   // local exclusive
    if (threadIdx.x == SCAN_B - 1) g_bsum[blockIdx.x] = s[SCAN_B - 1];
}

__global__ void k_scan2() {  // single thread: 98 adds
    int run = 0;
    for (int b = 0; b < NB_SCAN; b++) {
        int v = g_bsum[b];
        g_bsum[b] = run;
        run += v;
    }
}

// ---- finalize scan + dinv1 (fused per-node pass) ----
__global__ void __launch_bounds__(256) k_scan3() {
    int i = blockIdx.x * 256 + threadIdx.x;
    if (i >= N_NODES) return;
    int b = g_base[i] + g_bsum[i / SCAN_B];
    g_base[i] = b;
    g_cur[i] = b;
    g_dinv1[i] = rsqrtf(g_deg[i] + 1.0f);
    if (i == 0) g_base[N_NODES] = N_EDGES;
}

// ---- bucket edges by destination column; also resolve argmin index ----
__global__ void __launch_bounds__(256) k_place(const void* __restrict__ ei,
                                               const float* __restrict__ ew) {
    int e = blockIdx.x * 256 + threadIdx.x;
    if (e >= N_EDGES) return;
    int r = load_row(ei, e);
    int c = load_col(ei, e);
    float w = ew[e];
    int pos = atomicAdd(&g_cur[c], 1);
    g_sre[pos] = make_int2(r, __float_as_int(w));
    if (r == 0 && __float_as_uint(w) == g_minbits)
        atomicMin(&g_minidx, e);   // first occurrence of the min (jnp.argmin)
}

// ---- extract deleted-edge info (single thread) ----
__global__ void k_extract(const void* __restrict__ ei,
                          const float* __restrict__ ew) {
    int idx = (g_minidx == 0x7FFFFFFF) ? 0 : g_minidx; // all-inf mask -> argmin 0
    g_wmin = ew[idx];
    g_target = load_col(ei, idx);
    g_zrow = load_row(ei, idx);
}

__global__ void __launch_bounds__(256) k_dinv2() {
    int i = blockIdx.x * 256 + threadIdx.x;
    if (i >= N_NODES) return;
    float sub = (i == g_target) ? g_wmin : 0.f;
    g_dinv2[i] = rsqrtf(g_deg[i] + 1.0f - sub);
}

// ---- layer-1 gather + epilogue: 16 lanes per node, shfl-staged metadata ----
// out = relu( dinv1[c] * sum_e dinv1[row]*w*h1[row]  +  dinv1[c]^2*h1[c] + b1 )
__global__ void __launch_bounds__(256) k_gather1(const float* __restrict__ b1) {
    int t = blockIdx.x * 256 + threadIdx.x;
    int node = t >> 4;
    int lane = t & 15;
    if (node >= N_NODES) return;   // never taken (1.6M threads exactly)
    unsigned hm = (threadIdx.x & 16) ? 0xffff0000u : 0x0000ffffu;
    int s = g_base[node], e_end = g_base[node + 1];

    float4 acc = make_float4(0.f, 0.f, 0.f, 0.f);
    for (int base = s; base < e_end; base += 16) {
        int n = min(16, e_end - base);
        int r0 = 0; float cf = 0.f;
        if (base + lane < e_end) {
            int2 md = g_sre[base + lane];          // coalesced 16x8B
            r0 = md.x;
            cf = g_dinv1[r0] * __int_as_float(md.y);
        }
        for (int j = 0; j < n; j++) {
            float coef = __shfl_sync(hm, cf, j, 16);
            int r = __shfl_sync(hm, r0, j, 16);
            float4 hv = g_h1[(size_t)r * H4 + lane];
            acc.x += coef * hv.x; acc.y += coef * hv.y;
            acc.z += coef * hv.z; acc.w += coef * hv.w;
        }
    }
    float dc = g_dinv1[node];
    float dc2 = dc * dc;
    float4 hme = g_h1[(size_t)node * H4 + lane];
    float4 bb = *(const float4*)&b1[lane * 4];
    float4 o;
    o.x = fmaxf(dc * acc.x + dc2 * hme.x + bb.x, 0.f);
    o.y = fmaxf(dc * acc.y + dc2 * hme.y + bb.y, 0.f);
    o.z = fmaxf(dc * acc.z + dc2 * hme.z + bb.z, 0.f);
    o.w = fmaxf(dc * acc.w + dc2 * hme.w + bb.w, 0.f);
    g_rel[(size_t)node * H4 + lane] = o;
}

// ---- GEMM2: g_h2 = g_rel @ W2 ----
__global__ void __launch_bounds__(256) k_gemm2(const float* __restrict__ W2) {
    __shared__ float4 Ws4[(HID * C_OUT) / 4]; // 256 float4
    if (threadIdx.x < (HID * C_OUT) / 4)
        Ws4[threadIdx.x] = ((const float4*)W2)[threadIdx.x];
    __syncthreads();
    const float* Ws = (const float*)Ws4;

    int row = blockIdx.x * 256 + threadIdx.x;
    if (row >= N_NODES) return;

    float acc[C_OUT];
#pragma unroll
    for (int j = 0; j < C_OUT; j++) acc[j] = 0.f;

    const float4* xr = &g_rel[(size_t)row * H4];
#pragma unroll
    for (int k4 = 0; k4 < HID / 4; k4++) {
        float4 xv = xr[k4];
        const float* wk = Ws + k4 * 4 * C_OUT;
#pragma unroll
        for (int j = 0; j < C_OUT; j += 4) {
            float4 w0 = *(const float4*)(wk + j);
            float4 w1 = *(const float4*)(wk + C_OUT + j);
            float4 w2 = *(const float4*)(wk + 2 * C_OUT + j);
            float4 w3 = *(const float4*)(wk + 3 * C_OUT + j);
            acc[j + 0] += xv.x * w0.x + xv.y * w1.x + xv.z * w2.x + xv.w * w3.x;
            acc[j + 1] += xv.x * w0.y + xv.y * w1.y + xv.z * w2.y + xv.w * w3.y;
            acc[j + 2] += xv.x * w0.z + xv.y * w1.z + xv.z * w2.z + xv.w * w3.z;
            acc[j + 3] += xv.x * w0.w + xv.y * w1.w + xv.z * w2.w + xv.w * w3.w;
        }
    }
    float4* outr = &g_h2[(size_t)row * C4];
#pragma unroll
    for (int j = 0; j < C_OUT; j += 4)
        outr[j / 4] = make_float4(acc[j], acc[j + 1], acc[j + 2], acc[j + 3]);
}

// ---- layer-2 gather + epilogue: 4 lanes per node; inline first-match skip
// of the deleted edge (same semantics as a zap pass: exactly one record with
// matching (row, weight-bits) in the target bucket contributes 0). ----
__global__ void __launch_bounds__(256) k_gather2(const float* __restrict__ b2,
                                                 float* __restrict__ out) {
    int t = blockIdx.x * 256 + threadIdx.x;
    int node = t >> 2;
    int lane = t & 3;
    if (node >= N_NODES) return;
    int s = g_base[node], e_end = g_base[node + 1];

    bool active = (node == g_target);   // this node owns the deleted edge
    int zr = g_zrow;
    int wb = __float_as_int(g_wmin);
    bool skipped = false;

    float4 acc = make_float4(0.f, 0.f, 0.f, 0.f);
    for (int e = s; e < e_end; e++) {
        int2 md = g_sre[e];
        if (active && !skipped && md.x == zr && md.y == wb) {
            skipped = true;            // deterministic: same order in all 4 lanes
            continue;
        }
        float coef = g_dinv2[md.x] * __int_as_float(md.y);
        float4 hv = g_h2[(size_t)md.x * C4 + lane];
        acc.x += coef * hv.x; acc.y += coef * hv.y;
        acc.z += coef * hv.z; acc.w += coef * hv.w;
    }
    float dc = g_dinv2[node];
    float dc2 = dc * dc;
    float4 hme = g_h2[(size_t)node * C4 + lane];
    float4 bb = *(const float4*)&b2[lane * 4];
    float4 o;
    o.x = dc * acc.x + dc2 * hme.x + bb.x;
    o.y = dc * acc.y + dc2 * hme.y + bb.y;
    o.z = dc * acc.z + dc2 * hme.z + bb.z;
    o.w = dc * acc.w + dc2 * hme.w + bb.w;
    ((float4*)out)[(size_t)node * C4 + lane] = o;
}

extern "C" void kernel_launch(void* const* d_in, const int* in_sizes, int n_in,
                              void* d_out, int out_size) {
    const float* x  = (const float*)d_in[0];
    const void*  ei = d_in[1];
    const float* ew = (const float*)d_in[2];
    const float* W1 = (const float*)d_in[3];
    const float* b1 = (const float*)d_in[4];
    const float* W2 = (const float*)d_in[5];
    const float* b2 = (const float*)d_in[6];
    float* out = (float*)d_out;

    (void)in_sizes; (void)n_in; (void)out_size;

    int nb_nodes = (N_NODES + 255) / 256;
    int nb_edges = (N_EDGES + 255) / 256;
    int nb_g1 = (N_NODES + G1_ROWS - 1) / G1_ROWS;

    // One-time side-stream/event creation (host resources only, no device
    // memory; created on the uncaptured correctness call, reused during
    // capture where the fork/join events become graph edges).
    static cudaStream_t sb = nullptr;
    static cudaEvent_t evFork = nullptr, evJoin = nullptr;
    if (sb == nullptr) {
        cudaStreamCreateWithFlags(&sb, cudaStreamNonBlocking);
        cudaEventCreateWithFlags(&evFork, cudaEventDisableTiming);
        cudaEventCreateWithFlags(&evJoin, cudaEventDisableTiming);
    }

    // Fork: gemm1 (x @ W1) is independent of the whole edge pipeline.
    cudaEventRecord(evFork, 0);
    cudaStreamWaitEvent(sb, evFork, 0);
    k_gemm1<<<nb_g1, 256, 0, sb>>>(x, W1);
    cudaEventRecord(evJoin, sb);

    // Main stream: edge pipeline.
    k_init<<<nb_nodes, 256>>>((const int*)ei);
    k_deg<<<nb_edges, 256>>>(ei, ew);
    k_scan1<<<NB_SCAN, SCAN_B>>>();
    k_scan2<<<1, 1>>>();
    k_scan3<<<nb_nodes, 256>>>();
    k_place<<<nb_edges, 256>>>(ei, ew);
    k_extract<<<1, 1>>>(ei, ew);
    k_dinv2<<<nb_nodes, 256>>>();

    // Join: gather1 needs both gemm1 (g_h1) and the edge pipeline.
    cudaStreamWaitEvent(0, evJoin, 0);
    k_gather1<<<(int)(((long)N_NODES * 16 + 255) / 256), 256>>>(b1);
    k_gemm2<<<nb_nodes, 256>>>(W2);
    k_gather2<<<(int)(((long)N_NODES * 4 + 255) / 256), 256>>>(b2, out);
}

// round 16
// speedup vs baseline: 1.2515x; 1.0719x over previous
#include <cuda_runtime.h>

#define N_NODES 100000
#define N_EDGES 1600000
#define F_IN 128
#define HID 64
#define C_OUT 16

#define H4 (HID / 4)      // 16 float4 per node (layer 1)
#define C4 (C_OUT / 4)    // 4  float4 per node (layer 2)

#define SCAN_B 1024
#define NB_SCAN ((N_NODES + SCAN_B - 1) / SCAN_B)   // 98

#define G1_ROWS 128       // rows per gemm1 block
#define G1_KC 32          // k-chunk
#define XS_STRIDE 36      // padded floats per row in x smem tile

// ---- static device scratch; float4-typed => guaranteed 16B alignment ----
__device__ float4 g_h1[(size_t)N_NODES * H4];    // x @ W1
__device__ float4 g_rel[(size_t)N_NODES * H4];   // relu(layer-1 output)
__device__ float4 g_h2[(size_t)N_NODES * C4];    // relu_h @ W2
__device__ float g_dinv1[N_NODES];
__device__ float g_dinv2[N_NODES];
__device__ int   g_cnt[N_NODES];
__device__ int   g_base[N_NODES + 1];
__device__ int   g_cur[N_NODES];
__device__ int   g_bsum[NB_SCAN];
__device__ int2  g_sre[N_EDGES];     // sorted (row, weight-bits) per edge
__device__ unsigned g_minbits;   // min float bit-pattern among row==0 edges
__device__ int   g_minidx;       // min edge index among bit-exact matches
__device__ float g_wmin;
__device__ int   g_target;       // col[deleted edge]
__device__ int   g_zrow;         // row[deleted edge]
__device__ int   g_is64;         // edge_index stored as int64?

// ---- dtype-robust edge_index accessors ----
__device__ __forceinline__ int load_row(const void* ei, int e) {
    if (g_is64) return (int)((const long long*)ei)[e];
    return ((const int*)ei)[e];
}
__device__ __forceinline__ int load_col(const void* ei, int e) {
    if (g_is64) return (int)((const long long*)ei)[(size_t)N_EDGES + e];
    return ((const int*)ei)[(size_t)N_EDGES + e];
}

// ---- init: zero counters, init argmin state, detect ei dtype ----
__global__ void __launch_bounds__(256) k_init(const int* __restrict__ ei32) {
    int i = blockIdx.x * 256 + threadIdx.x;
    if (i == 0) {
        g_minbits = 0xFFFFFFFFu;
        g_minidx = 0x7FFFFFFF;
        // int64 layout has all-zero odd 32-bit words (indices < 2^31)
        int allzero = 1;
        for (int j = 0; j < 64; j++)
            if (ei32[2 * j + 1] != 0) { allzero = 0; break; }
        g_is64 = allzero;
    }
    if (i < N_NODES) g_cnt[i] = 0;
}

// ---- per-col edge count + min-weight bits among row==0 edges.
// (degrees are computed later from the sorted buckets — no float atomics) ----
__global__ void __launch_bounds__(256) k_deg(const void* __restrict__ ei,
                                             const float* __restrict__ ew) {
    int e = blockIdx.x * 256 + threadIdx.x;
    if (e >= N_EDGES) return;
    int c = load_col(ei, e);
    atomicAdd(&g_cnt[c], 1);
    int r = load_row(ei, e);
    if (r == 0) {
        // weights are non-negative: IEEE bit pattern is order-preserving.
        atomicMin(&g_minbits, __float_as_uint(ew[e]));
    }
}

// ==== GEMM1 (R7 algorithm, occupancy-tuned): f32x2 packed along N ====
// Block: 128 rows x 64 cols. Thread (tr = tid>>4, tc = tid&15) computes
// rows {i*16 + tr, i=0..7} x cols {tc*4 .. tc*4+3}. Accumulators are 16 f32x2.
// Inner loop loads xv per-row (not staged in an 8-wide array) to cut live
// registers; __launch_bounds__(256,3) targets 3 blocks/SM (24 warps).
union F4U2 { float4 f4; unsigned long long u2[2]; };

__device__ __forceinline__ void fma2(unsigned long long& acc,
                                     unsigned long long a,
                                     unsigned long long b) {
    asm("fma.rn.f32x2 %0, %1, %2, %0;" : "+l"(acc) : "l"(a), "l"(b));
}
__device__ __forceinline__ unsigned long long dup2(float v) {
    unsigned long long d;
    asm("mov.b64 %0, {%1, %1};" : "=l"(d) : "f"(v));
    return d;
}

__global__ void __launch_bounds__(256, 3) k_gemm1(const float* __restrict__ x,
                                                  const float* __restrict__ W1) {
    __shared__ float Xs[G1_ROWS * XS_STRIDE];   // 18432 B
    __shared__ float Wcs[G1_KC * HID];          // 8192 B

    const int tid = threadIdx.x;
    const int tc = tid & 15;
    const int tr = tid >> 4;
    const int rb = blockIdx.x * G1_ROWS;

    unsigned long long acc[8][2];
#pragma unroll
    for (int i = 0; i < 8; i++) { acc[i][0] = 0ULL; acc[i][1] = 0ULL; }

    for (int kc = 0; kc < F_IN / G1_KC; kc++) {
        const int k0 = kc * G1_KC;
        // fill W chunk: rows k0..k0+31 of W1 are contiguous (row-major [128][64])
#pragma unroll
        for (int i = tid; i < (G1_KC * HID) / 4; i += 256)
            *(float4*)&Wcs[i * 4] = ((const float4*)(W1 + k0 * HID))[i];
        // fill X chunk: 128 rows x 32 k
#pragma unroll
        for (int i = tid; i < G1_ROWS * (G1_KC / 4); i += 256) {
            int r = i >> 3, seg = i & 7;
            float4 v = make_float4(0.f, 0.f, 0.f, 0.f);
            if (rb + r < N_NODES)
                v = *(const float4*)&x[(size_t)(rb + r) * F_IN + k0 + seg * 4];
            *(float4*)&Xs[r * XS_STRIDE + seg * 4] = v;
        }
        __syncthreads();

#pragma unroll
        for (int k4 = 0; k4 < G1_KC / 4; k4++) {
            F4U2 wv[4];
#pragma unroll
            for (int kk = 0; kk < 4; kk++)
                wv[kk].f4 = *(const float4*)&Wcs[(k4 * 4 + kk) * HID + tc * 4];
#pragma unroll
            for (int i = 0; i < 8; i++) {
                float4 xv = *(const float4*)&Xs[(i * 16 + tr) * XS_STRIDE + k4 * 4];
                unsigned long long a;
                a = dup2(xv.x); fma2(acc[i][0], a, wv[0].u2[0]); fma2(acc[i][1], a, wv[0].u2[1]);
                a = dup2(xv.y); fma2(acc[i][0], a, wv[1].u2[0]); fma2(acc[i][1], a, wv[1].u2[1]);
                a = dup2(xv.z); fma2(acc[i][0], a, wv[2].u2[0]); fma2(acc[i][1], a, wv[2].u2[1]);
                a = dup2(xv.w); fma2(acc[i][0], a, wv[3].u2[0]); fma2(acc[i][1], a, wv[3].u2[1]);
            }
        }
        __syncthreads();
    }

    // epilogue: unpack and store float4 per (row, col-group)
#pragma unroll
    for (int i = 0; i < 8; i++) {
        int row = rb + i * 16 + tr;
        if (row < N_NODES) {
            F4U2 o;
            o.u2[0] = acc[i][0];
            o.u2[1] = acc[i][1];
            g_h1[(size_t)row * H4 + tc] = o.f4;
        }
    }
}

// ---- exclusive scan of g_cnt -> g_base ----
__global__ void __launch_bounds__(SCAN_B) k_scan1() {
    __shared__ int s[SCAN_B];
    int i = blockIdx.x * SCAN_B + threadIdx.x;
    int v = (i < N_NODES) ? g_cnt[i] : 0;
    s[threadIdx.x] = v;
    __syncthreads();
    for (int off = 1; off < SCAN_B; off <<= 1) {   // Hillis-Steele inclusive
        int t = (threadIdx.x >= off) ? s[threadIdx.x - off] : 0;
        __syncthreads();
        s[threadIdx.x] += t;
        __syncthreads();
    }
    if (i < N_NODES) g_base[i] = s[threadIdx.x] - v;   // local exclusive
    if (threadIdx.x == SCAN_B - 1) g_bsum[blockIdx.x] = s[SCAN_B - 1];
}

__global__ void k_scan2() {  // single thread: 98 adds
    int run = 0;
    for (int b = 0; b < NB_SCAN; b++) {
        int v = g_bsum[b];
        g_bsum[b] = run;
        run += v;
    }
}

// ---- finalize scan (per-node pass) ----
__global__ void __launch_bounds__(256) k_scan3() {
    int i = blockIdx.x * 256 + threadIdx.x;
    if (i >= N_NODES) return;
    int b = g_base[i] + g_bsum[i / SCAN_B];
    g_base[i] = b;
    g_cur[i] = b;
    if (i == 0) g_base[N_NODES] = N_EDGES;
}

// ---- bucket edges by destination column; also resolve argmin index ----
__global__ void __launch_bounds__(256) k_place(const void* __restrict__ ei,
                                               const float* __restrict__ ew) {
    int e = blockIdx.x * 256 + threadIdx.x;
    if (e >= N_EDGES) return;
    int r = load_row(ei, e);
    int c = load_col(ei, e);
    float w = ew[e];
    int pos = atomicAdd(&g_cur[c], 1);
    g_sre[pos] = make_int2(r, __float_as_int(w));
    if (r == 0 && __float_as_uint(w) == g_minbits)
        atomicMin(&g_minidx, e);   // first occurrence of the min (jnp.argmin)
}

// ---- extract deleted-edge info (single thread) ----
__global__ void k_extract(const void* __restrict__ ei,
                          const float* __restrict__ ew) {
    int idx = (g_minidx == 0x7FFFFFFF) ? 0 : g_minidx; // all-inf mask -> argmin 0
    g_wmin = ew[idx];
    g_target = load_col(ei, idx);
    g_zrow = load_row(ei, idx);
}

// ---- degrees from sorted buckets (coalesced, no atomics) + dinv1 + dinv2.
// 8 lanes per node, shfl-reduce within the 8-lane group. ----
__global__ void __launch_bounds__(256) k_degdinv() {
    int t = blockIdx.x * 256 + threadIdx.x;
    int node = t >> 3;
    int lane = t & 7;
    if (node >= N_NODES) return;   // exact: 800k threads
    int s = g_base[node], e_end = g_base[node + 1];
    float sum = 0.f;
    for (int i = s + lane; i < e_end; i += 8)
        sum += __int_as_float(g_sre[i].y);
#pragma unroll
    for (int off = 4; off; off >>= 1)
        sum += __shfl_xor_sync(0xffffffffu, sum, off, 8);
    if (lane == 0) {
        float d = sum + 1.0f;
        g_dinv1[node] = rsqrtf(d);
        float sub = (node == g_target) ? g_wmin : 0.f;
        g_dinv2[node] = rsqrtf(d - sub);
    }
}

// ---- layer-1 gather + epilogue: 16 lanes per node, shfl-staged metadata ----
// out = relu( dinv1[c] * sum_e dinv1[row]*w*h1[row]  +  dinv1[c]^2*h1[c] + b1 )
__global__ void __launch_bounds__(256) k_gather1(const float* __restrict__ b1) {
    int t = blockIdx.x * 256 + threadIdx.x;
    int node = t >> 4;
    int lane = t & 15;
    if (node >= N_NODES) return;   // never taken (1.6M threads exactly)
    unsigned hm = (threadIdx.x & 16) ? 0xffff0000u : 0x0000ffffu;
    int s = g_base[node], e_end = g_base[node + 1];

    float4 acc = make_float4(0.f, 0.f, 0.f, 0.f);
    for (int base = s; base < e_end; base += 16) {
        int n = min(16, e_end - base);
        int r0 = 0; float cf = 0.f;
        if (base + lane < e_end) {
            int2 md = g_sre[base + lane];          // coalesced 16x8B
            r0 = md.x;
            cf = g_dinv1[r0] * __int_as_float(md.y);
        }
        for (int j = 0; j < n; j++) {
            float coef = __shfl_sync(hm, cf, j, 16);
            int r = __shfl_sync(hm, r0, j, 16);
            float4 hv = g_h1[(size_t)r * H4 + lane];
            acc.x += coef * hv.x; acc.y += coef * hv.y;
            acc.z += coef * hv.z; acc.w += coef * hv.w;
        }
    }
    float dc = g_dinv1[node];
    float dc2 = dc * dc;
    float4 hme = g_h1[(size_t)node * H4 + lane];
    float4 bb = *(const float4*)&b1[lane * 4];
    float4 o;
    o.x = fmaxf(dc * acc.x + dc2 * hme.x + bb.x, 0.f);
    o.y = fmaxf(dc * acc.y + dc2 * hme.y + bb.y, 0.f);
    o.z = fmaxf(dc * acc.z + dc2 * hme.z + bb.z, 0.f);
    o.w = fmaxf(dc * acc.w + dc2 * hme.w + bb.w, 0.f);
    g_rel[(size_t)node * H4 + lane] = o;
}

// ---- GEMM2: g_h2 = g_rel @ W2 ----
__global__ void __launch_bounds__(256) k_gemm2(const float* __restrict__ W2) {
    __shared__ float4 Ws4[(HID * C_OUT) / 4]; // 256 float4
    if (threadIdx.x < (HID * C_OUT) / 4)
        Ws4[threadIdx.x] = ((const float4*)W2)[threadIdx.x];
    __syncthreads();
    const float* Ws = (const float*)Ws4;

    int row = blockIdx.x * 256 + threadIdx.x;
    if (row >= N_NODES) return;

    float acc[C_OUT];
#pragma unroll
    for (int j = 0; j < C_OUT; j++) acc[j] = 0.f;

    const float4* xr = &g_rel[(size_t)row * H4];
#pragma unroll
    for (int k4 = 0; k4 < HID / 4; k4++) {
        float4 xv = xr[k4];
        const float* wk = Ws + k4 * 4 * C_OUT;
#pragma unroll
        for (int j = 0; j < C_OUT; j += 4) {
            float4 w0 = *(const float4*)(wk + j);
            float4 w1 = *(const float4*)(wk + C_OUT + j);
            float4 w2 = *(const float4*)(wk + 2 * C_OUT + j);
            float4 w3 = *(const float4*)(wk + 3 * C_OUT + j);
            acc[j + 0] += xv.x * w0.x + xv.y * w1.x + xv.z * w2.x + xv.w * w3.x;
            acc[j + 1] += xv.x * w0.y + xv.y * w1.y + xv.z * w2.y + xv.w * w3.y;
            acc[j + 2] += xv.x * w0.z + xv.y * w1.z + xv.z * w2.z + xv.w * w3.z;
            acc[j + 3] += xv.x * w0.w + xv.y * w1.w + xv.z * w2.w + xv.w * w3.w;
        }
    }
    float4* outr = &g_h2[(size_t)row * C4];
#pragma unroll
    for (int j = 0; j < C_OUT; j += 4)
        outr[j / 4] = make_float4(acc[j], acc[j + 1], acc[j + 2], acc[j + 3]);
}

// ---- layer-2 gather + epilogue: 4 lanes per node; inline first-match skip
// of the deleted edge (same semantics as a zap pass: exactly one record with
// matching (row, weight-bits) in the target bucket contributes 0). ----
__global__ void __launch_bounds__(256) k_gather2(const float* __restrict__ b2,
                                                 float* __restrict__ out) {
    int t = blockIdx.x * 256 + threadIdx.x;
    int node = t >> 2;
    int lane = t & 3;
    if (node >= N_NODES) return;
    int s = g_base[node], e_end = g_base[node + 1];

    bool active = (node == g_target);   // this node owns the deleted edge
    int zr = g_zrow;
    int wb = __float_as_int(g_wmin);
    bool skipped = false;

    float4 acc = make_float4(0.f, 0.f, 0.f, 0.f);
    for (int e = s; e < e_end; e++) {
        int2 md = g_sre[e];
        if (active && !skipped && md.x == zr && md.y == wb) {
            skipped = true;            // deterministic: same order in all 4 lanes
            continue;
        }
        float coef = g_dinv2[md.x] * __int_as_float(md.y);
        float4 hv = g_h2[(size_t)md.x * C4 + lane];
        acc.x += coef * hv.x; acc.y += coef * hv.y;
        acc.z += coef * hv.z; acc.w += coef * hv.w;
    }
    float dc = g_dinv2[node];
    float dc2 = dc * dc;
    float4 hme = g_h2[(size_t)node * C4 + lane];
    float4 bb = *(const float4*)&b2[lane * 4];
    float4 o;
    o.x = dc * acc.x + dc2 * hme.x + bb.x;
    o.y = dc * acc.y + dc2 * hme.y + bb.y;
    o.z = dc * acc.z + dc2 * hme.z + bb.z;
    o.w = dc * acc.w + dc2 * hme.w + bb.w;
    ((float4*)out)[(size_t)node * C4 + lane] = o;
}

extern "C" void kernel_launch(void* const* d_in, const int* in_sizes, int n_in,
                              void* d_out, int out_size) {
    const float* x  = (const float*)d_in[0];
    const void*  ei = d_in[1];
    const float* ew = (const float*)d_in[2];
    const float* W1 = (const float*)d_in[3];
    const float* b1 = (const float*)d_in[4];
    const float* W2 = (const float*)d_in[5];
    const float* b2 = (const float*)d_in[6];
    float* out = (float*)d_out;

    (void)in_sizes; (void)n_in; (void)out_size;

    int nb_nodes = (N_NODES + 255) / 256;
    int nb_edges = (N_EDGES + 255) / 256;
    int nb_g1 = (N_NODES + G1_ROWS - 1) / G1_ROWS;

    // One-time side-stream/event creation (host resources only, no device
    // memory; created on the uncaptured correctness call, reused during
    // capture where the fork/join events become graph edges).
    static cudaStream_t sb = nullptr;
    static cudaEvent_t evFork = nullptr, evJoin = nullptr;
    if (sb == nullptr) {
        cudaStreamCreateWithFlags(&sb, cudaStreamNonBlocking);
        cudaEventCreateWithFlags(&evFork, cudaEventDisableTiming);
        cudaEventCreateWithFlags(&evJoin, cudaEventDisableTiming);
    }

    // Fork: gemm1 (x @ W1) is independent of the whole edge pipeline.
    cudaEventRecord(evFork, 0);
    cudaStreamWaitEvent(sb, evFork, 0);
    k_gemm1<<<nb_g1, 256, 0, sb>>>(x, W1);
    cudaEventRecord(evJoin, sb);

    // Main stream: edge pipeline.
    k_init<<<nb_nodes, 256>>>((const int*)ei);
    k_deg<<<nb_edges, 256>>>(ei, ew);
    k_scan1<<<NB_SCAN, SCAN_B>>>();
    k_scan2<<<1, 1>>>();
    k_scan3<<<nb_nodes, 256>>>();
    k_place<<<nb_edges, 256>>>(ei, ew);
    k_extract<<<1, 1>>>(ei, ew);
    k_degdinv<<<(int)(((long)N_NODES * 8 + 255) / 256), 256>>>();

    // Join: gather1 needs both gemm1 (g_h1) and the edge pipeline.
    cudaStreamWaitEvent(0, evJoin, 0);
    k_gather1<<<(int)(((long)N_NODES * 16 + 255) / 256), 256>>>(b1);
    k_gemm2<<<nb_nodes, 256>>>(W2);
    k_gather2<<<(int)(((long)N_NODES * 4 + 255) / 256), 256>>>(b2, out);
}

// round 17
// speedup vs baseline: 1.2695x; 1.0144x over previous
#include <cuda_runtime.h>

#define N_NODES 100000
#define N_EDGES 1600000
#define F_IN 128
#define HID 64
#define C_OUT 16

#define H4 (HID / 4)      // 16 float4 per node (layer 1)
#define C4 (C_OUT / 4)    // 4  float4 per node (layer 2)

#define SCAN_B 1024
#define NB_SCAN ((N_NODES + SCAN_B - 1) / SCAN_B)   // 98

#define G1_ROWS 128       // rows per gemm1 block
#define G1_KC 32          // k-chunk
#define XS_STRIDE 36      // padded floats per row in x smem tile

// ---- static device scratch; float4-typed => guaranteed 16B alignment ----
__device__ float4 g_h1[(size_t)N_NODES * H4];    // x @ W1
__device__ float4 g_rel[(size_t)N_NODES * H4];   // relu(layer-1 output)
__device__ float4 g_h2[(size_t)N_NODES * C4];    // relu_h @ W2
__device__ float g_dinv1[N_NODES];
__device__ float g_dinv2[N_NODES];
__device__ int4  g_cnt4[(N_NODES + 3) / 4];      // g_cnt viewed as int4
__device__ int   g_base[N_NODES + 1];
__device__ int   g_cur[N_NODES];
__device__ int   g_bsum[NB_SCAN];
__device__ int2  g_sre[N_EDGES];     // sorted (row, weight-bits) per edge
__device__ unsigned g_minbits;   // min float bit-pattern among row==0 edges
__device__ int   g_minidx;       // min edge index among bit-exact matches
__device__ float g_wmin;
__device__ int   g_target;       // col[deleted edge]
__device__ int   g_zrow;         // row[deleted edge]
__device__ int   g_is64;         // edge_index stored as int64?

#define g_cnt ((int*)g_cnt4)

// ---- dtype-robust edge_index accessors ----
__device__ __forceinline__ int load_row(const void* ei, int e) {
    if (g_is64) return (int)((const long long*)ei)[e];
    return ((const int*)ei)[e];
}
__device__ __forceinline__ int load_col(const void* ei, int e) {
    if (g_is64) return (int)((const long long*)ei)[(size_t)N_EDGES + e];
    return ((const int*)ei)[(size_t)N_EDGES + e];
}
// paired loads for even e (16B/8B aligned by construction)
__device__ __forceinline__ void load_row2(const void* ei, int e, int& a, int& b) {
    if (g_is64) {
        longlong2 v = *(const longlong2*)((const long long*)ei + e);
        a = (int)v.x; b = (int)v.y;
    } else {
        int2 v = *(const int2*)((const int*)ei + e);
        a = v.x; b = v.y;
    }
}
__device__ __forceinline__ void load_col2(const void* ei, int e, int& a, int& b) {
    if (g_is64) {
        longlong2 v = *(const longlong2*)((const long long*)ei + (size_t)N_EDGES + e);
        a = (int)v.x; b = (int)v.y;
    } else {
        int2 v = *(const int2*)((const int*)ei + (size_t)N_EDGES + e);
        a = v.x; b = v.y;
    }
}

// ---- init: zero counters (int4), init argmin state, detect ei dtype ----
__global__ void __launch_bounds__(256) k_init(const int* __restrict__ ei32) {
    int i = blockIdx.x * 256 + threadIdx.x;
    if (i == 0) {
        g_minbits = 0xFFFFFFFFu;
        g_minidx = 0x7FFFFFFF;
        // int64 layout has all-zero odd 32-bit words (indices < 2^31)
        int allzero = 1;
        for (int j = 0; j < 64; j++)
            if (ei32[2 * j + 1] != 0) { allzero = 0; break; }
        g_is64 = allzero;
    }
    if (i < (N_NODES + 3) / 4) g_cnt4[i] = make_int4(0, 0, 0, 0);
}

// ---- per-col edge count + min-weight bits among row==0 edges (2 edges/thr) ----
__global__ void __launch_bounds__(256) k_deg(const void* __restrict__ ei,
                                             const float* __restrict__ ew) {
    int e = (blockIdx.x * 256 + threadIdx.x) * 2;
    if (e >= N_EDGES) return;
    int c0, c1, r0, r1;
    load_col2(ei, e, c0, c1);
    load_row2(ei, e, r0, r1);
    atomicAdd(&g_cnt[c0], 1);
    atomicAdd(&g_cnt[c1], 1);
    // weights are non-negative: IEEE bit pattern is order-preserving.
    if (r0 == 0) atomicMin(&g_minbits, __float_as_uint(ew[e]));
    if (r1 == 0) atomicMin(&g_minbits, __float_as_uint(ew[e + 1]));
}

// ==== GEMM1 (R15-proven): f32x2 packed along N, 3 blocks/SM ====
union F4U2 { float4 f4; unsigned long long u2[2]; };

__device__ __forceinline__ void fma2(unsigned long long& acc,
                                     unsigned long long a,
                                     unsigned long long b) {
    asm("fma.rn.f32x2 %0, %1, %2, %0;" : "+l"(acc) : "l"(a), "l"(b));
}
__device__ __forceinline__ unsigned long long dup2(float v) {
    unsigned long long d;
    asm("mov.b64 %0, {%1, %1};" : "=l"(d) : "f"(v));
    return d;
}

__global__ void __launch_bounds__(256, 3) k_gemm1(const float* __restrict__ x,
                                                  const float* __restrict__ W1) {
    __shared__ float Xs[G1_ROWS * XS_STRIDE];   // 18432 B
    __shared__ float Wcs[G1_KC * HID];          // 8192 B

    const int tid = threadIdx.x;
    const int tc = tid & 15;
    const int tr = tid >> 4;
    const int rb = blockIdx.x * G1_ROWS;

    unsigned long long acc[8][2];
#pragma unroll
    for (int i = 0; i < 8; i++) { acc[i][0] = 0ULL; acc[i][1] = 0ULL; }

    for (int kc = 0; kc < F_IN / G1_KC; kc++) {
        const int k0 = kc * G1_KC;
#pragma unroll
        for (int i = tid; i < (G1_KC * HID) / 4; i += 256)
            *(float4*)&Wcs[i * 4] = ((const float4*)(W1 + k0 * HID))[i];
#pragma unroll
        for (int i = tid; i < G1_ROWS * (G1_KC / 4); i += 256) {
            int r = i >> 3, seg = i & 7;
            float4 v = make_float4(0.f, 0.f, 0.f, 0.f);
            if (rb + r < N_NODES)
                v = *(const float4*)&x[(size_t)(rb + r) * F_IN + k0 + seg * 4];
            *(float4*)&Xs[r * XS_STRIDE + seg * 4] = v;
        }
        __syncthreads();

#pragma unroll
        for (int k4 = 0; k4 < G1_KC / 4; k4++) {
            F4U2 wv[4];
#pragma unroll
            for (int kk = 0; kk < 4; kk++)
                wv[kk].f4 = *(const float4*)&Wcs[(k4 * 4 + kk) * HID + tc * 4];
#pragma unroll
            for (int i = 0; i < 8; i++) {
                float4 xv = *(const float4*)&Xs[(i * 16 + tr) * XS_STRIDE + k4 * 4];
                unsigned long long a;
                a = dup2(xv.x); fma2(acc[i][0], a, wv[0].u2[0]); fma2(acc[i][1], a, wv[0].u2[1]);
                a = dup2(xv.y); fma2(acc[i][0], a, wv[1].u2[0]); fma2(acc[i][1], a, wv[1].u2[1]);
                a = dup2(xv.z); fma2(acc[i][0], a, wv[2].u2[0]); fma2(acc[i][1], a, wv[2].u2[1]);
                a = dup2(xv.w); fma2(acc[i][0], a, wv[3].u2[0]); fma2(acc[i][1], a, wv[3].u2[1]);
            }
        }
        __syncthreads();
    }

#pragma unroll
    for (int i = 0; i < 8; i++) {
        int row = rb + i * 16 + tr;
        if (row < N_NODES) {
            F4U2 o;
            o.u2[0] = acc[i][0];
            o.u2[1] = acc[i][1];
            g_h1[(size_t)row * H4 + tc] = o.f4;
        }
    }
}

// ---- exclusive scan of g_cnt -> g_base (warp-shfl based) ----
__global__ void __launch_bounds__(SCAN_B) k_scan1() {
    __shared__ int wsum[SCAN_B / 32];
    int i = blockIdx.x * SCAN_B + threadIdx.x;
    int lane = threadIdx.x & 31;
    int wid = threadIdx.x >> 5;
    int v = (i < N_NODES) ? g_cnt[i] : 0;

    // warp-inclusive scan
    int inc = v;
#pragma unroll
    for (int off = 1; off < 32; off <<= 1) {
        int t = __shfl_up_sync(0xffffffffu, inc, off);
        if (lane >= off) inc += t;
    }
    if (lane == 31) wsum[wid] = inc;
    __syncthreads();
    if (wid == 0) {
        int ws = (lane < SCAN_B / 32) ? wsum[lane] : 0;
#pragma unroll
        for (int off = 1; off < 32; off <<= 1) {
            int t = __shfl_up_sync(0xffffffffu, ws, off);
            if (lane >= off) ws += t;
        }
        if (lane < SCAN_B / 32) wsum[lane] = ws;   // inclusive warp prefix
    }
    __syncthreads();
    int wpre = (wid > 0) ? wsum[wid - 1] : 0;
    if (i < N_NODES) g_base[i] = wpre + inc - v;   // exclusive
    if (threadIdx.x == SCAN_B - 1) g_bsum[blockIdx.x] = wpre + inc;
}

__global__ void k_scan2() {  // single thread: 98 adds
    int run = 0;
    for (int b = 0; b < NB_SCAN; b++) {
        int v = g_bsum[b];
        g_bsum[b] = run;
        run += v;
    }
}

// ---- finalize scan (per-node pass) ----
__global__ void __launch_bounds__(256) k_scan3() {
    int i = blockIdx.x * 256 + threadIdx.x;
    if (i >= N_NODES) return;
    int b = g_base[i] + g_bsum[i / SCAN_B];
    g_base[i] = b;
    g_cur[i] = b;
    if (i == 0) g_base[N_NODES] = N_EDGES;
}

// ---- bucket edges by destination column (2 edges/thread); argmin index ----
__global__ void __launch_bounds__(256) k_place(const void* __restrict__ ei,
                                               const float* __restrict__ ew) {
    int e = (blockIdx.x * 256 + threadIdx.x) * 2;
    if (e >= N_EDGES) return;
    int r0, r1, c0, c1;
    load_row2(ei, e, r0, r1);
    load_col2(ei, e, c0, c1);
    float2 w = *(const float2*)&ew[e];
    int p0 = atomicAdd(&g_cur[c0], 1);
    g_sre[p0] = make_int2(r0, __float_as_int(w.x));
    int p1 = atomicAdd(&g_cur[c1], 1);
    g_sre[p1] = make_int2(r1, __float_as_int(w.y));
    if (r0 == 0 && __float_as_uint(w.x) == g_minbits)
        atomicMin(&g_minidx, e);       // first occurrence of the min (jnp.argmin)
    if (r1 == 0 && __float_as_uint(w.y) == g_minbits)
        atomicMin(&g_minidx, e + 1);
}

// ---- extract deleted-edge info (single thread) ----
__global__ void k_extract(const void* __restrict__ ei,
                          const float* __restrict__ ew) {
    int idx = (g_minidx == 0x7FFFFFFF) ? 0 : g_minidx; // all-inf mask -> argmin 0
    g_wmin = ew[idx];
    g_target = load_col(ei, idx);
    g_zrow = load_row(ei, idx);
}

// ---- degrees from sorted buckets (coalesced, no atomics) + dinv1 + dinv2.
// 8 lanes per node, shfl-reduce within the 8-lane group. ----
__global__ void __launch_bounds__(256) k_degdinv() {
    int t = blockIdx.x * 256 + threadIdx.x;
    int node = t >> 3;
    int lane = t & 7;
    if (node >= N_NODES) return;   // exact: 800k threads
    int s = g_base[node], e_end = g_base[node + 1];
    float sum = 0.f;
    for (int i = s + lane; i < e_end; i += 8)
        sum += __int_as_float(g_sre[i].y);
#pragma unroll
    for (int off = 4; off; off >>= 1)
        sum += __shfl_xor_sync(0xffffffffu, sum, off, 8);
    if (lane == 0) {
        float d = sum + 1.0f;
        g_dinv1[node] = rsqrtf(d);
        float sub = (node == g_target) ? g_wmin : 0.f;
        g_dinv2[node] = rsqrtf(d - sub);
    }
}

// ---- layer-1 gather + epilogue: 16 lanes per node, shfl-staged metadata ----
// out = relu( dinv1[c] * sum_e dinv1[row]*w*h1[row]  +  dinv1[c]^2*h1[c] + b1 )
__global__ void __launch_bounds__(256) k_gather1(const float* __restrict__ b1) {
    int t = blockIdx.x * 256 + threadIdx.x;
    int node = t >> 4;
    int lane = t & 15;
    if (node >= N_NODES) return;   // never taken (1.6M threads exactly)
    unsigned hm = (threadIdx.x & 16) ? 0xffff0000u : 0x0000ffffu;
    int s = g_base[node], e_end = g_base[node + 1];

    float4 acc = make_float4(0.f, 0.f, 0.f, 0.f);
    for (int base = s; base < e_end; base += 16) {
        int n = min(16, e_end - base);
        int r0 = 0; float cf = 0.f;
        if (base + lane < e_end) {
            int2 md = g_sre[base + lane];          // coalesced 16x8B
            r0 = md.x;
            cf = g_dinv1[r0] * __int_as_float(md.y);
        }
        for (int j = 0; j < n; j++) {
            float coef = __shfl_sync(hm, cf, j, 16);
            int r = __shfl_sync(hm, r0, j, 16);
            float4 hv = g_h1[(size_t)r * H4 + lane];
            acc.x += coef * hv.x; acc.y += coef * hv.y;
            acc.z += coef * hv.z; acc.w += coef * hv.w;
        }
    }
    float dc = g_dinv1[node];
    float dc2 = dc * dc;
    float4 hme = g_h1[(size_t)node * H4 + lane];
    float4 bb = *(const float4*)&b1[lane * 4];
    float4 o;
    o.x = fmaxf(dc * acc.x + dc2 * hme.x + bb.x, 0.f);
    o.y = fmaxf(dc * acc.y + dc2 * hme.y + bb.y, 0.f);
    o.z = fmaxf(dc * acc.z + dc2 * hme.z + bb.z, 0.f);
    o.w = fmaxf(dc * acc.w + dc2 * hme.w + bb.w, 0.f);
    g_rel[(size_t)node * H4 + lane] = o;
}

// ---- GEMM2: g_h2 = g_rel @ W2 ----
__global__ void __launch_bounds__(256) k_gemm2(const float* __restrict__ W2) {
    __shared__ float4 Ws4[(HID * C_OUT) / 4]; // 256 float4
    if (threadIdx.x < (HID * C_OUT) / 4)
        Ws4[threadIdx.x] = ((const float4*)W2)[threadIdx.x];
    __syncthreads();
    const float* Ws = (const float*)Ws4;

    int row = blockIdx.x * 256 + threadIdx.x;
    if (row >= N_NODES) return;

    float acc[C_OUT];
#pragma unroll
    for (int j = 0; j < C_OUT; j++) acc[j] = 0.f;

    const float4* xr = &g_rel[(size_t)row * H4];
#pragma unroll
    for (int k4 = 0; k4 < HID / 4; k4++) {
        float4 xv = xr[k4];
        const float* wk = Ws + k4 * 4 * C_OUT;
#pragma unroll
        for (int j = 0; j < C_OUT; j += 4) {
            float4 w0 = *(const float4*)(wk + j);
            float4 w1 = *(const float4*)(wk + C_OUT + j);
            float4 w2 = *(const float4*)(wk + 2 * C_OUT + j);
            float4 w3 = *(const float4*)(wk + 3 * C_OUT + j);
            acc[j + 0] += xv.x * w0.x + xv.y * w1.x + xv.z * w2.x + xv.w * w3.x;
            acc[j + 1] += xv.x * w0.y + xv.y * w1.y + xv.z * w2.y + xv.w * w3.y;
            acc[j + 2] += xv.x * w0.z + xv.y * w1.z + xv.z * w2.z + xv.w * w3.z;
            acc[j + 3] += xv.x * w0.w + xv.y * w1.w + xv.z * w2.w + xv.w * w3.w;
        }
    }
    float4* outr = &g_h2[(size_t)row * C4];
#pragma unroll
    for (int j = 0; j < C_OUT; j += 4)
        outr[j / 4] = make_float4(acc[j], acc[j + 1], acc[j + 2], acc[j + 3]);
}

// ---- layer-2 gather + epilogue: 4 lanes per node; inline first-match skip
// of the deleted edge (same semantics as a zap pass: exactly one record with
// matching (row, weight-bits) in the target bucket contributes 0). ----
__global__ void __launch_bounds__(256) k_gather2(const float* __restrict__ b2,
                                                 float* __restrict__ out) {
    int t = blockIdx.x * 256 + threadIdx.x;
    int node = t >> 2;
    int lane = t & 3;
    if (node >= N_NODES) return;
    int s = g_base[node], e_end = g_base[node + 1];

    bool active = (node == g_target);   // this node owns the deleted edge
    int zr = g_zrow;
    int wb = __float_as_int(g_wmin);
    bool skipped = false;

    float4 acc = make_float4(0.f, 0.f, 0.f, 0.f);
    for (int e = s; e < e_end; e++) {
        int2 md = g_sre[e];
        if (active && !skipped && md.x == zr && md.y == wb) {
            skipped = true;            // deterministic: same order in all 4 lanes
            continue;
        }
        float coef = g_dinv2[md.x] * __int_as_float(md.y);
        float4 hv = g_h2[(size_t)md.x * C4 + lane];
        acc.x += coef * hv.x; acc.y += coef * hv.y;
        acc.z += coef * hv.z; acc.w += coef * hv.w;
    }
    float dc = g_dinv2[node];
    float dc2 = dc * dc;
    float4 hme = g_h2[(size_t)node * C4 + lane];
    float4 bb = *(const float4*)&b2[lane * 4];
    float4 o;
    o.x = dc * acc.x + dc2 * hme.x + bb.x;
    o.y = dc * acc.y + dc2 * hme.y + bb.y;
    o.z = dc * acc.z + dc2 * hme.z + bb.z;
    o.w = dc * acc.w + dc2 * hme.w + bb.w;
    ((float4*)out)[(size_t)node * C4 + lane] = o;
}

extern "C" void kernel_launch(void* const* d_in, const int* in_sizes, int n_in,
                              void* d_out, int out_size) {
    const float* x  = (const float*)d_in[0];
    const void*  ei = d_in[1];
    const float* ew = (const float*)d_in[2];
    const float* W1 = (const float*)d_in[3];
    const float* b1 = (const float*)d_in[4];
    const float* W2 = (const float*)d_in[5];
    const float* b2 = (const float*)d_in[6];
    float* out = (float*)d_out;

    (void)in_sizes; (void)n_in; (void)out_size;

    int nb_nodes = (N_NODES + 255) / 256;
    int nb_init  = ((N_NODES + 3) / 4 + 255) / 256;
    int nb_edge2 = (N_EDGES / 2 + 255) / 256;
    int nb_g1 = (N_NODES + G1_ROWS - 1) / G1_ROWS;

    // One-time side-stream/event creation (host resources only, no device
    // memory; created on the uncaptured correctness call, reused during
    // capture where the fork/join events become graph edges).
    static cudaStream_t sb = nullptr;
    static cudaEvent_t evFork = nullptr, evJoin = nullptr;
    if (sb == nullptr) {
        cudaStreamCreateWithFlags(&sb, cudaStreamNonBlocking);
        cudaEventCreateWithFlags(&evFork, cudaEventDisableTiming);
        cudaEventCreateWithFlags(&evJoin, cudaEventDisableTiming);
    }

    // Fork: gemm1 (x @ W1) is independent of the whole edge pipeline.
    cudaEventRecord(evFork, 0);
    cudaStreamWaitEvent(sb, evFork, 0);
    k_gemm1<<<nb_g1, 256, 0, sb>>>(x, W1);
    cudaEventRecord(evJoin, sb);

    // Main stream: edge pipeline.
    k_init<<<nb_init, 256>>>((const int*)ei);
    k_deg<<<nb_edge2, 256>>>(ei, ew);
    k_scan1<<<NB_SCAN, SCAN_B>>>();
    k_scan2<<<1, 1>>>();
    k_scan3<<<nb_nodes, 256>>>();
    k_place<<<nb_edge2, 256>>>(ei, ew);
    k_extract<<<1, 1>>>(ei, ew);
    k_degdinv<<<(int)(((long)N_NODES * 8 + 255) / 256), 256>>>();

    // Join: gather1 needs both gemm1 (g_h1) and the edge pipeline.
    cudaStreamWaitEvent(0, evJoin, 0);
    k_gather1<<<(int)(((long)N_NODES * 16 + 255) / 256), 256>>>(b1);
    k_gemm2<<<nb_nodes, 256>>>(W2);
    k_gather2<<<(int)(((long)N_NODES * 4 + 255) / 256), 256>>>(b2, out);
}